// round 1
// baseline (speedup 1.0000x reference)
#include <cuda_runtime.h>
#include <cuda_bf16.h>
#include <math.h>

#define N_NODES 100000
#define N_EDGES 1600000
#define IN_CH   128
#define HID     128
#define OUT_CH  64

// ---------------- scratch (device globals; no allocation allowed) ----------
__device__ float g_h[(size_t)N_NODES * HID];      // transformed + src-scaled features
__device__ float g_agg[(size_t)N_NODES * HID];    // aggregated / activated output
__device__ float g_dinv[N_NODES];
__device__ int   g_deg[N_NODES];
__device__ int   g_rowptr[N_NODES + 1];
__device__ int   g_cursor[N_NODES];
__device__ int   g_csr[N_EDGES];
#define POOL_BLOCKS 240
__device__ float g_partial[POOL_BLOCKS * OUT_CH];

// ---------------- CSR build ------------------------------------------------
__global__ void zero_deg_kernel() {
    int i = blockIdx.x * blockDim.x + threadIdx.x;
    if (i < N_NODES) g_deg[i] = 0;
}

__global__ void count_deg_kernel(const int* __restrict__ ei) {
    int e = blockIdx.x * blockDim.x + threadIdx.x;
    if (e < N_EDGES) atomicAdd(&g_deg[ei[N_EDGES + e]], 1);
}

__global__ void dinv_kernel() {
    int i = blockIdx.x * blockDim.x + threadIdx.x;
    if (i < N_NODES) g_dinv[i] = rsqrtf((float)(g_deg[i] + 1));  // +1 self-loop
}

// single-block exclusive scan over g_deg -> g_rowptr, g_cursor
__global__ void scan_kernel() {
    __shared__ int partial[1024];
    const int t = threadIdx.x;
    const int chunk = (N_NODES + 1023) / 1024;  // 98
    int start = t * chunk;
    int end = start + chunk; if (end > N_NODES) end = N_NODES;
    if (start > N_NODES) start = N_NODES;

    int s = 0;
    for (int i = start; i < end; i++) s += g_deg[i];
    partial[t] = s;
    __syncthreads();
    // Hillis-Steele inclusive scan
    for (int off = 1; off < 1024; off <<= 1) {
        int v = 0;
        if (t >= off) v = partial[t - off];
        __syncthreads();
        if (t >= off) partial[t] += v;
        __syncthreads();
    }
    int pre = (t == 0) ? 0 : partial[t - 1];
    for (int i = start; i < end; i++) {
        g_rowptr[i] = pre;
        g_cursor[i] = pre;
        pre += g_deg[i];
    }
    if (t == 1023) g_rowptr[N_NODES] = pre;  // == total edges
}

__global__ void fill_csr_kernel(const int* __restrict__ ei) {
    int e = blockIdx.x * blockDim.x + threadIdx.x;
    if (e < N_EDGES) {
        int dst = ei[N_EDGES + e];
        int pos = atomicAdd(&g_cursor[dst], 1);
        g_csr[pos] = ei[e];
    }
}

// ---------------- GEMM: out[m][n] = dinv[m] * sum_k A[m][k]*W[k][n] ---------
// K = 128 fixed. BM=128, BK=16, 8x8 micro-tile.
template <int BN>
__global__ void gemm_scale_kernel(const float* __restrict__ A,
                                  const float* __restrict__ W,
                                  float* __restrict__ out, int M) {
    constexpr int BM = 128, BK = 16;
    constexpr int TX = BN / 8;       // 16 or 8
    constexpr int NT = TX * (BM / 8);

    __shared__ float As[BK][BM];     // transposed: As[k][m]
    __shared__ float Bs[BK][BN];

    const int tid = threadIdx.x;
    const int tx = tid % TX, ty = tid / TX;
    const int m0 = blockIdx.x * BM;

    float acc[8][8];
#pragma unroll
    for (int i = 0; i < 8; i++)
#pragma unroll
        for (int j = 0; j < 8; j++) acc[i][j] = 0.f;

    for (int k0 = 0; k0 < 128; k0 += BK) {
        // A tile: BM x BK, stored transposed
#pragma unroll
        for (int i = tid; i < BM * BK / 4; i += NT) {
            int m = i / (BK / 4);
            int kk4 = (i % (BK / 4)) * 4;
            int row = m0 + m;
            float4 v = make_float4(0.f, 0.f, 0.f, 0.f);
            if (row < M)
                v = *reinterpret_cast<const float4*>(&A[(size_t)row * 128 + k0 + kk4]);
            As[kk4 + 0][m] = v.x;
            As[kk4 + 1][m] = v.y;
            As[kk4 + 2][m] = v.z;
            As[kk4 + 3][m] = v.w;
        }
        // B tile: BK x BN
#pragma unroll
        for (int i = tid; i < BK * BN / 4; i += NT) {
            int kk = i / (BN / 4);
            int n4 = (i % (BN / 4)) * 4;
            *reinterpret_cast<float4*>(&Bs[kk][n4]) =
                *reinterpret_cast<const float4*>(&W[(size_t)(k0 + kk) * BN + n4]);
        }
        __syncthreads();

#pragma unroll
        for (int kk = 0; kk < BK; kk++) {
            float a[8], b[8];
            *reinterpret_cast<float4*>(&a[0]) = *reinterpret_cast<float4*>(&As[kk][ty * 8]);
            *reinterpret_cast<float4*>(&a[4]) = *reinterpret_cast<float4*>(&As[kk][ty * 8 + 4]);
            *reinterpret_cast<float4*>(&b[0]) = *reinterpret_cast<float4*>(&Bs[kk][tx * 8]);
            *reinterpret_cast<float4*>(&b[4]) = *reinterpret_cast<float4*>(&Bs[kk][tx * 8 + 4]);
#pragma unroll
            for (int i = 0; i < 8; i++)
#pragma unroll
                for (int j = 0; j < 8; j++) acc[i][j] += a[i] * b[j];
        }
        __syncthreads();
    }

#pragma unroll
    for (int i = 0; i < 8; i++) {
        int row = m0 + ty * 8 + i;
        if (row < M) {
            float d = g_dinv[row];
#pragma unroll
            for (int j4 = 0; j4 < 8; j4 += 4) {
                float4 v;
                v.x = acc[i][j4 + 0] * d;
                v.y = acc[i][j4 + 1] * d;
                v.z = acc[i][j4 + 2] * d;
                v.w = acc[i][j4 + 3] * d;
                *reinterpret_cast<float4*>(&out[(size_t)row * BN + tx * 8 + j4]) = v;
            }
        }
    }
}

// ---------------- SpMM (warp per dst node) ----------------------------------
// out[i] = act( dinv[i] * (h[i] + sum_{src in csr row i} h[src]) + bias )
template <int C, bool RELU>
__global__ void spmm_kernel(const float* __restrict__ h,
                            const float* __restrict__ bias,
                            float* __restrict__ out) {
    constexpr int V = C / 32;  // floats per lane (4 or 2)
    int gw = (blockIdx.x * blockDim.x + threadIdx.x) >> 5;
    int lane = threadIdx.x & 31;
    if (gw >= N_NODES) return;

    int beg = g_rowptr[gw];
    int end = g_rowptr[gw + 1];

    float acc[V];
    // self loop
    {
        const float* hp = &h[(size_t)gw * C + lane * V];
        if (V == 4) {
            float4 v = *reinterpret_cast<const float4*>(hp);
            acc[0] = v.x; acc[1] = v.y; acc[2] = v.z; acc[3] = v.w;
        } else {
            float2 v = *reinterpret_cast<const float2*>(hp);
            acc[0] = v.x; acc[1] = v.y;
        }
    }

    int j = beg;
    for (; j + 1 < end; j += 2) {
        int s0 = g_csr[j];
        int s1 = g_csr[j + 1];
        if (V == 4) {
            float4 v0 = *reinterpret_cast<const float4*>(&h[(size_t)s0 * C + lane * 4]);
            float4 v1 = *reinterpret_cast<const float4*>(&h[(size_t)s1 * C + lane * 4]);
            acc[0] += v0.x + v1.x; acc[1] += v0.y + v1.y;
            acc[2] += v0.z + v1.z; acc[3] += v0.w + v1.w;
        } else {
            float2 v0 = *reinterpret_cast<const float2*>(&h[(size_t)s0 * C + lane * 2]);
            float2 v1 = *reinterpret_cast<const float2*>(&h[(size_t)s1 * C + lane * 2]);
            acc[0] += v0.x + v1.x; acc[1] += v0.y + v1.y;
        }
    }
    if (j < end) {
        int s0 = g_csr[j];
        if (V == 4) {
            float4 v0 = *reinterpret_cast<const float4*>(&h[(size_t)s0 * C + lane * 4]);
            acc[0] += v0.x; acc[1] += v0.y; acc[2] += v0.z; acc[3] += v0.w;
        } else {
            float2 v0 = *reinterpret_cast<const float2*>(&h[(size_t)s0 * C + lane * 2]);
            acc[0] += v0.x; acc[1] += v0.y;
        }
    }

    float d = g_dinv[gw];
#pragma unroll
    for (int v = 0; v < V; v++) {
        float val = acc[v] * d + bias[lane * V + v];
        if (RELU) val = fmaxf(val, 0.f);
        acc[v] = val;
    }
    if (V == 4) {
        float4 o = make_float4(acc[0], acc[1], acc[2], acc[3]);
        *reinterpret_cast<float4*>(&out[(size_t)gw * C + lane * 4]) = o;
    } else {
        float2 o = make_float2(acc[0], acc[1]);
        *reinterpret_cast<float2*>(&out[(size_t)gw * C + lane * 2]) = o;
    }
}

// ---------------- min pool --------------------------------------------------
__global__ void min_part_kernel(const float* __restrict__ g) {
    int c = threadIdx.x & 63;
    int r = threadIdx.x >> 6;  // 0..3
    float m = 3.4028235e38f;
    for (int row = blockIdx.x * 4 + r; row < N_NODES; row += gridDim.x * 4)
        m = fminf(m, g[(size_t)row * OUT_CH + c]);
    __shared__ float sm[256];
    sm[threadIdx.x] = m;
    __syncthreads();
    if (threadIdx.x < 128) sm[threadIdx.x] = fminf(sm[threadIdx.x], sm[threadIdx.x + 128]);
    __syncthreads();
    if (threadIdx.x < 64)
        g_partial[blockIdx.x * OUT_CH + threadIdx.x] =
            fminf(sm[threadIdx.x], sm[threadIdx.x + 64]);
}

__global__ void min_final_kernel(float* __restrict__ out) {
    int c = threadIdx.x;  // 64
    float m = 3.4028235e38f;
    for (int b = 0; b < POOL_BLOCKS; b++) m = fminf(m, g_partial[b * OUT_CH + c]);
    out[c] = m;
}

// ---------------- launch ----------------------------------------------------
extern "C" void kernel_launch(void* const* d_in, const int* in_sizes, int n_in,
                              void* d_out, int out_size) {
    const float* x  = (const float*)d_in[0];
    const int*   ei = (const int*)  d_in[1];
    const float* W1 = (const float*)d_in[2];
    const float* b1 = (const float*)d_in[3];
    const float* W2 = (const float*)d_in[4];
    const float* b2 = (const float*)d_in[5];
    const float* W3 = (const float*)d_in[6];
    const float* b3 = (const float*)d_in[7];
    float* out = (float*)d_out;

    float *h_ptr = nullptr, *agg_ptr = nullptr;
    cudaGetSymbolAddress((void**)&h_ptr, g_h);
    cudaGetSymbolAddress((void**)&agg_ptr, g_agg);

    const int TPB = 256;
    // CSR build
    zero_deg_kernel<<<(N_NODES + TPB - 1) / TPB, TPB>>>();
    count_deg_kernel<<<(N_EDGES + TPB - 1) / TPB, TPB>>>(ei);
    dinv_kernel<<<(N_NODES + TPB - 1) / TPB, TPB>>>();
    scan_kernel<<<1, 1024>>>();
    fill_csr_kernel<<<(N_EDGES + TPB - 1) / TPB, TPB>>>(ei);

    const int gemm_blocks = (N_NODES + 127) / 128;
    const int spmm_blocks = (N_NODES * 32 + TPB - 1) / TPB;

    // Layer 1: h = (x @ W1) * dinv ; agg = relu(dinv*(agg_sum) + b1)
    gemm_scale_kernel<128><<<gemm_blocks, 256>>>(x, W1, h_ptr, N_NODES);
    spmm_kernel<128, true><<<spmm_blocks, TPB>>>(h_ptr, b1, agg_ptr);

    // Layer 2
    gemm_scale_kernel<128><<<gemm_blocks, 256>>>(agg_ptr, W2, h_ptr, N_NODES);
    spmm_kernel<128, true><<<spmm_blocks, TPB>>>(h_ptr, b2, agg_ptr);

    // Layer 3 (no relu, 64 out channels)
    gemm_scale_kernel<64><<<gemm_blocks, 128>>>(agg_ptr, W3, h_ptr, N_NODES);
    spmm_kernel<64, false><<<spmm_blocks, TPB>>>(h_ptr, b3, agg_ptr);

    // min pool
    min_part_kernel<<<POOL_BLOCKS, 256>>>(agg_ptr);
    min_final_kernel<<<1, 64>>>(out);
}